// round 6
// baseline (speedup 1.0000x reference)
#include <cuda_runtime.h>
#include <math.h>

#define Hdim 768
#define Ldim 2
#define Vdim 32000
#define Bdim 128
#define Tdim 64
#define Sdim 32
#define G4   (4 * Hdim)   // 3072

// persistent-LSTM tiling
#define NBLK 96           // blocks; each owns 8 hidden columns
#define JPB  8            // j columns per block
#define NT   32           // gate columns per block (4 gates x 8 j)
#define WPAD 36           // smem stride for W slice (conflict-reduced, 16B aligned)
#define GPAD 33           // smem stride for gates exchange

// ---------------- scratch (device globals; no allocation allowed) -----------
__device__ __align__(16) float g_xs   [Tdim * Bdim * Hdim];
__device__ __align__(16) float g_ys0  [Tdim * Bdim * Hdim];
__device__ __align__(16) float g_ys1  [Tdim * Bdim * Hdim];
__device__ __align__(16) float g_xproj[Tdim * Bdim * G4];
__device__ __align__(16) float g_hA   [Bdim * Hdim];
__device__ __align__(16) float g_hB   [Bdim * Hdim];
__device__ unsigned g_bar;

// ---------------- embeddings ------------------------------------------------
__global__ void embed_trg_kernel(const int* __restrict__ trg,
                                 const float* __restrict__ emb,
                                 float* __restrict__ xs) {
    int idx = blockIdx.x * blockDim.x + threadIdx.x;
    if (idx >= Tdim * Bdim * Hdim) return;
    int j = idx % Hdim;
    int r = idx / Hdim;        // r = t*B + b
    int b = r % Bdim;
    int t = r / Bdim;
    int tok = trg[b * Tdim + t];
    xs[idx] = emb[(size_t)tok * Hdim + j];
}

__global__ void init_h_kernel(const int* __restrict__ src,
                              const float* __restrict__ bert,
                              float* __restrict__ h) {
    int idx = blockIdx.x * blockDim.x + threadIdx.x;
    if (idx >= Bdim * Hdim) return;
    int b = idx / Hdim, j = idx % Hdim;
    int tok = src[b * Sdim];   // src[:,0]
    h[idx] = bert[(size_t)tok * Hdim + j];
}

// ---------------- 128x128x16 SGEMM: C = A(MxK) * Bm(NxK)^T + bias ----------
template <bool REMAP>
__global__ void sgemm128_kernel(const float* __restrict__ A,
                                const float* __restrict__ Bm,
                                float* __restrict__ C,
                                int N, int K,
                                const float* __restrict__ bias1,
                                const float* __restrict__ bias2) {
    __shared__ float As[16][128];
    __shared__ float Bs[16][128];
    const int tid = threadIdx.x;          // 256 threads
    const int tx = tid & 15, ty = tid >> 4;
    const int m0 = blockIdx.y * 128, n0 = blockIdx.x * 128;

    float acc[8][8];
#pragma unroll
    for (int i = 0; i < 8; i++)
#pragma unroll
        for (int j = 0; j < 8; j++) acc[i][j] = 0.f;

    for (int kt = 0; kt < K; kt += 16) {
#pragma unroll
        for (int it = 0; it < 2; it++) {
            int lin = tid + it * 256;
            int r  = lin >> 2;
            int k4 = (lin & 3) << 2;
            float4 va = *reinterpret_cast<const float4*>(A + (size_t)(m0 + r) * K + kt + k4);
            As[k4 + 0][r] = va.x; As[k4 + 1][r] = va.y;
            As[k4 + 2][r] = va.z; As[k4 + 3][r] = va.w;
            float4 vb = *reinterpret_cast<const float4*>(Bm + (size_t)(n0 + r) * K + kt + k4);
            Bs[k4 + 0][r] = vb.x; Bs[k4 + 1][r] = vb.y;
            Bs[k4 + 2][r] = vb.z; Bs[k4 + 3][r] = vb.w;
        }
        __syncthreads();
#pragma unroll
        for (int k = 0; k < 16; k++) {
            float4 a0 = *reinterpret_cast<const float4*>(&As[k][ty * 8]);
            float4 a1 = *reinterpret_cast<const float4*>(&As[k][ty * 8 + 4]);
            float4 b0 = *reinterpret_cast<const float4*>(&Bs[k][tx * 8]);
            float4 b1 = *reinterpret_cast<const float4*>(&Bs[k][tx * 8 + 4]);
            float a[8] = {a0.x, a0.y, a0.z, a0.w, a1.x, a1.y, a1.z, a1.w};
            float b[8] = {b0.x, b0.y, b0.z, b0.w, b1.x, b1.y, b1.z, b1.w};
#pragma unroll
            for (int i = 0; i < 8; i++)
#pragma unroll
                for (int j = 0; j < 8; j++) acc[i][j] = fmaf(a[i], b[j], acc[i][j]);
        }
        __syncthreads();
    }

#pragma unroll
    for (int i = 0; i < 8; i++) {
        int r = m0 + ty * 8 + i;
        int orow = REMAP ? ((r & (Bdim - 1)) * Tdim + (r >> 7)) : r;
#pragma unroll
        for (int j = 0; j < 8; j++) {
            int col = n0 + tx * 8 + j;
            float bv = 0.f;
            if (bias1) bv += bias1[col];
            if (bias2) bv += bias2[col];
            C[(size_t)orow * N + col] = acc[i][j] + bv;
        }
    }
}

// ---------------- fused persistent LSTM layer -------------------------------
// Grid = 96 blocks (all co-resident: 1 CTA/SM, 96 < 148 SMs), 256 threads.
// Block bx owns j-columns [bx*8, bx*8+8) => gate columns {seg*768 + j0 + jj}.
// W_hh slice (32x768) lives in SMEM for the whole kernel. One software grid
// barrier per timestep; h ping-pongs between two global buffers (read .cg,
// since L1 is not coherent across the hand-rolled barrier). c stays in regs.
__device__ __forceinline__ float sigmoidf_(float x) { return 1.f / (1.f + expf(-x)); }

__global__ void lstm_persistent_kernel(const float* __restrict__ Whh,   // [3072][768]
                                       const float* __restrict__ xproj, // [T*128][3072] incl. biases
                                       float* __restrict__ hA,          // holds h0 on entry
                                       float* __restrict__ hB,
                                       float* __restrict__ ys,          // [T][128][768]
                                       unsigned* __restrict__ bar) {
    extern __shared__ float sm[];
    float* Ws = sm;                       // [768][WPAD]  (uses first NT cols)
    float* As = Ws + 768 * WPAD;          // [16][128]
    float* Gs = As + 16 * 128;            // [128][GPAD]

    const int tid = threadIdx.x;
    const int tx = tid & 7;               // n-tile (4 cols each)
    const int ty = tid >> 3;              // m-tile (4 rows each), 0..31
    const int j0 = blockIdx.x * JPB;

    // Load W_hh slice once: Ws[k][n] = Whh[seg*768 + j0 + jj][k], n = seg*8+jj
#pragma unroll
    for (int n = 0; n < NT; n++) {
        int seg = n >> 3, jj = n & 7;
        const float* wrow = Whh + (size_t)(seg * Hdim + j0 + jj) * Hdim;
        for (int k = tid; k < Hdim; k += 256)
            Ws[k * WPAD + n] = wrow[k];
    }

    // per-thread cell state: element e -> (b, jj) with idx = tid + 256*e
    float creg[4] = {0.f, 0.f, 0.f, 0.f};

    __syncthreads();

    for (int t = 0; t < Tdim; t++) {
        const float* hcur = (t & 1) ? hB : hA;
        float*       hnxt = (t & 1) ? hA : hB;

        float acc[4][4];
#pragma unroll
        for (int i = 0; i < 4; i++)
#pragma unroll
            for (int j = 0; j < 4; j++) acc[i][j] = 0.f;

        for (int kt = 0; kt < Hdim; kt += 16) {
            __syncthreads();
#pragma unroll
            for (int it = 0; it < 2; it++) {
                int lin = tid + it * 256;
                int r  = lin >> 2;               // batch row 0..127
                int k4 = (lin & 3) << 2;
                float4 v = __ldcg(reinterpret_cast<const float4*>(
                    hcur + (size_t)r * Hdim + kt + k4));
                As[(k4 + 0) * 128 + r] = v.x;
                As[(k4 + 1) * 128 + r] = v.y;
                As[(k4 + 2) * 128 + r] = v.z;
                As[(k4 + 3) * 128 + r] = v.w;
            }
            __syncthreads();
#pragma unroll
            for (int k = 0; k < 16; k++) {
                float4 av = *reinterpret_cast<const float4*>(&As[k * 128 + ty * 4]);
                float4 bv = *reinterpret_cast<const float4*>(&Ws[(kt + k) * WPAD + tx * 4]);
                float a[4] = {av.x, av.y, av.z, av.w};
                float b[4] = {bv.x, bv.y, bv.z, bv.w};
#pragma unroll
                for (int i = 0; i < 4; i++)
#pragma unroll
                    for (int j = 0; j < 4; j++) acc[i][j] = fmaf(a[i], b[j], acc[i][j]);
            }
        }

        // epilogue: add xproj (incl. biases), exchange via smem, cell update
        {
            int n  = tx * 4;                     // 0,4,...,28 (stays inside one gate seg)
            int seg = n >> 3, jj = n & 7;
            size_t gcol = (size_t)seg * Hdim + j0 + jj;
            __syncthreads();                     // Gs free from previous step
#pragma unroll
            for (int i = 0; i < 4; i++) {
                int m = ty * 4 + i;              // batch row
                float4 x = *reinterpret_cast<const float4*>(
                    xproj + (size_t)(t * Bdim + m) * G4 + gcol);
                Gs[m * GPAD + n + 0] = acc[i][0] + x.x;
                Gs[m * GPAD + n + 1] = acc[i][1] + x.y;
                Gs[m * GPAD + n + 2] = acc[i][2] + x.z;
                Gs[m * GPAD + n + 3] = acc[i][3] + x.w;
            }
        }
        __syncthreads();

#pragma unroll
        for (int e = 0; e < 4; e++) {
            int idx = tid + 256 * e;             // 0..1023
            int b  = idx >> 3;
            int jj = idx & 7;
            float gi = Gs[b * GPAD +            jj];
            float gf = Gs[b * GPAD +  8 +       jj];
            float gg = Gs[b * GPAD + 16 +       jj];
            float go = Gs[b * GPAD + 24 +       jj];
            float i_ = sigmoidf_(gi);
            float f_ = sigmoidf_(gf);
            float g_ = tanhf(gg);
            float o_ = sigmoidf_(go);
            float cn = f_ * creg[e] + i_ * g_;
            creg[e] = cn;
            float hn = o_ * tanhf(cn);
            size_t off = (size_t)b * Hdim + j0 + jj;
            hnxt[off] = hn;
            ys[(size_t)t * Bdim * Hdim + off] = hn;
        }

        // grid barrier (release writes, then arrive; all blocks co-resident)
        __threadfence();
        __syncthreads();
        if (tid == 0) {
            atomicAdd(bar, 1u);
            unsigned target = (unsigned)gridDim.x * (unsigned)(t + 1);
            while (*((volatile unsigned*)bar) < target) { }
        }
        __syncthreads();
        __threadfence();
    }
}

// ---------------- launcher ---------------------------------------------------
extern "C" void kernel_launch(void* const* d_in, const int* in_sizes, int n_in,
                              void* d_out, int out_size) {
    const int*   src   = (const int*)  d_in[0];
    const int*   trg   = (const int*)  d_in[1];
    const float* bert  = (const float*)d_in[2];
    const float* emb   = (const float*)d_in[3];
    const float* W_ih  = (const float*)d_in[4];
    const float* W_hh  = (const float*)d_in[5];
    const float* b_ih  = (const float*)d_in[6];
    const float* b_hh  = (const float*)d_in[7];
    const float* W_out = (const float*)d_in[8];
    const float* b_out = (const float*)d_in[9];
    float* out = (float*)d_out;

    float *xs, *ys0, *ys1, *xproj, *hA, *hB;
    unsigned* bar;
    cudaGetSymbolAddress((void**)&xs,    g_xs);
    cudaGetSymbolAddress((void**)&ys0,   g_ys0);
    cudaGetSymbolAddress((void**)&ys1,   g_ys1);
    cudaGetSymbolAddress((void**)&xproj, g_xproj);
    cudaGetSymbolAddress((void**)&hA,    g_hA);
    cudaGetSymbolAddress((void**)&hB,    g_hB);
    cudaGetSymbolAddress((void**)&bar,   g_bar);

    const size_t smem_bytes = (768 * WPAD + 16 * 128 + 128 * GPAD) * sizeof(float);
    cudaFuncSetAttribute(lstm_persistent_kernel,
                         cudaFuncAttributeMaxDynamicSharedMemorySize,
                         (int)smem_bytes);

    // 1. embed targets -> xs[t][b][h]
    embed_trg_kernel<<<(Tdim * Bdim * Hdim + 255) / 256, 256>>>(trg, emb, xs);

    // 2. two LSTM layers; input projections hoisted into one big GEMM per layer
    for (int l = 0; l < Ldim; l++) {
        const float* Wi = W_ih + (size_t)l * G4 * Hdim;
        const float* Wh = W_hh + (size_t)l * G4 * Hdim;
        const float* bi = b_ih + (size_t)l * G4;
        const float* bh = b_hh + (size_t)l * G4;
        const float* inp = (l == 0) ? xs : ys0;
        float* ys = (l == 0) ? ys0 : ys1;

        // xproj[t,b,:] = inp[t,b,:] @ Wi^T + bi + bh   (8192 x 3072, K=768)
        sgemm128_kernel<false><<<dim3(G4 / 128, (Tdim * Bdim) / 128), 256>>>(
            inp, Wi, xproj, G4, Hdim, bi, bh);

        // h0 = bert[src[:,0]]
        init_h_kernel<<<(Bdim * Hdim + 255) / 256, 256>>>(src, bert, hA);

        // reset grid barrier, run whole recurrence in one launch
        cudaMemsetAsync(bar, 0, sizeof(unsigned));
        lstm_persistent_kernel<<<NBLK, 256, smem_bytes>>>(Wh, xproj, hA, hB, ys, bar);
    }

    // 3. logits: out[b,t,v] = ys1[t,b,:] . W_out[v,:] + b_out[v]
    sgemm128_kernel<true><<<dim3(Vdim / 128, (Tdim * Bdim) / 128), 256>>>(
        ys1, W_out, out, Vdim, Hdim, b_out, nullptr);
}